// round 15
// baseline (speedup 1.0000x reference)
#include <cuda_runtime.h>
#include <math.h>

#define NGRID   64
#define NG3     (64*64*64)
#define ALPHA   0.34f
#define COULOMB 138.935456f
#define CUTOFF2 81.0f
#define PI_F    3.14159265358979323846f
#define DTILE   128

// ---------------- device scratch (zero-initialized at module load) ----------------
__device__ float2 d_grid[NG3];      // spread grid; zeroed by k_fft_zx each run
__device__ float2 d_grid2[NG3];     // zx output; fully overwritten each run
__device__ double g_edir;           // reset by k_final each run
__device__ double g_erec;           // reset by k_final each run

// Abramowitz-Stegun 7.1.26: |err| <= 1.5e-7 absolute, x >= 0
__device__ __forceinline__ float fast_erfc(float x) {
    float t = __fdividef(1.0f, fmaf(0.3275911f, x, 1.0f));
    float p = fmaf(1.061405429f, t, -1.453152027f);
    p = fmaf(p, t, 1.421413741f);
    p = fmaf(p, t, -0.284496736f);
    p = fmaf(p, t, 0.254829592f);
    return p * t * __expf(-x * x);
}

// ---------------- direct space (triangular 128x128 tiles, orthorhombic) ----------------
__global__ void __launch_bounds__(DTILE) k_direct(const float* __restrict__ pos,
                                                  const float* __restrict__ q,
                                                  const int* __restrict__ excl,
                                                  const float* __restrict__ box, int N) {
    const int bi = blockIdx.x, bj = blockIdx.y;
    if (bj < bi) return;
    __shared__ float4 sp[DTILE];
    const int tx = threadIdx.x;
    const int i  = bi * DTILE + tx;
    const int jb = bj * DTILE;

    int jl = jb + tx;
    sp[tx] = make_float4(pos[3*jl + 0], pos[3*jl + 1], pos[3*jl + 2], q[jl]);
    __syncthreads();

    const float Lx = box[0], Ly = box[4], Lz = box[8];
    const float iLx = __fdividef(1.f, Lx), iLy = __fdividef(1.f, Ly), iLz = __fdividef(1.f, Lz);

    const float pxi = pos[3*i + 0], pyi = pos[3*i + 1], pzi = pos[3*i + 2];
    const float qi  = q[i];
    const int e0 = excl[2*i + 0];
    const int e1 = excl[2*i + 1];

    float pacc = 0.f;
#pragma unroll 4
    for (int jj = 0; jj < DTILE; jj++) {
        float4 pj = sp[jj];
        float dx = pxi - pj.x;
        float dy = pyi - pj.y;
        float dz = pzi - pj.z;
        dx -= Lx * rintf(dx * iLx);
        dy -= Ly * rintf(dy * iLy);
        dz -= Lz * rintf(dz * iLz);
        float r2 = dx*dx + dy*dy + dz*dz;
        int jg = jb + jj;
        if (r2 < CUTOFF2 && jg != i && jg != e0 && jg != e1) {
            float rinv = rsqrtf(r2);
            pacc += pj.w * fast_erfc(ALPHA * r2 * rinv) * rinv;
        }
    }
    pacc *= qi;

    float eacc = 0.f;
    if (bi == bj) {
        eacc += -COULOMB * ALPHA * 0.5641895835477563f * qi * qi;  // self
#pragma unroll
        for (int s = 0; s < 2; s++) {
            int e = (s == 0) ? e0 : e1;
            if (e >= 0) {
                float dx = pxi - pos[3*e + 0];
                float dy = pyi - pos[3*e + 1];
                float dz = pzi - pos[3*e + 2];
                dx -= Lx * rintf(dx * iLx);
                dy -= Ly * rintf(dy * iLy);
                dz -= Lz * rintf(dz * iLz);
                float r2 = dx*dx + dy*dy + dz*dz;
                if (r2 > 0.f) {
                    float rinv = rsqrtf(r2);
                    float r = r2 * rinv;
                    eacc += -0.5f * COULOMB * qi * q[e] * erff(ALPHA * r) * rinv;
                }
            }
        }
    }

    float wt = (bi == bj) ? 0.5f : 1.0f;
    float tot = COULOMB * wt * pacc + eacc;
#pragma unroll
    for (int off = 16; off > 0; off >>= 1)
        tot += __shfl_down_sync(0xffffffffu, tot, off);
    if ((tx & 31) == 0)
        atomicAdd(&g_edir, (double)tot);
}

// ---------------- B-spline spread (order 4), one thread per (atom, x-offset) ----------
__global__ void k_spread(const float* __restrict__ pos, const float* __restrict__ q,
                         const float* __restrict__ box, int N) {
    int idx = blockIdx.x * blockDim.x + threadIdx.x;
    int i = idx >> 2;
    int a = idx & 3;
    if (i >= N) return;

    const float iLx = __fdividef(1.f, box[0]);
    const float iLy = __fdividef(1.f, box[4]);
    const float iLz = __fdividef(1.f, box[8]);

    float f0 = pos[3*i + 0] * iLx;
    float f1 = pos[3*i + 1] * iLy;
    float f2 = pos[3*i + 2] * iLz;
    f0 -= floorf(f0); f1 -= floorf(f1); f2 -= floorf(f2);

    float u[3] = { f0 * NGRID, f1 * NGRID, f2 * NGRID };
    int   base[3];
    float w[3][4];
#pragma unroll
    for (int d = 0; d < 3; d++) {
        float fu = floorf(u[d]);
        base[d] = (int)fu;
        float t = u[d] - fu;
        float w2_0 = 1.f - t, w2_1 = t;
        float n0 = 0.5f * (1.f - t) * w2_0;
        float n1 = 0.5f * ((t + 1.f) * w2_0 + (2.f - t) * w2_1);
        float n2 = 0.5f * t * w2_1;
        w[d][3] = (1.f/3.f) * t * n2;
        w[d][2] = (1.f/3.f) * ((t + 1.f) * n1 + (3.f - t) * n2);
        w[d][1] = (1.f/3.f) * ((t + 2.f) * n0 + (2.f - t) * n1);
        w[d][0] = (1.f/3.f) * (1.f - t) * n0;
    }
    int ix = (base[0] + a + 61) & 63;
    float qa = q[i] * w[0][a];
#pragma unroll
    for (int b = 0; b < 4; b++) {
        int iy = (base[1] + b + 61) & 63;
        float qab = qa * w[1][b];
#pragma unroll
        for (int c = 0; c < 4; c++) {
            int iz = (base[2] + c + 61) & 63;
            int flat = ((ix << 6) | iy) << 6 | iz;
            atomicAdd(&d_grid[flat].x, qab * w[2][c]);
        }
    }
}

// ---------------- register-resident 64-pt DIF FFT (warp collective, out bit-reversed) ----
__device__ __forceinline__ void bfly_local(float2& a, float2& b, float2 w) {
    float dr = a.x - b.x, di = a.y - b.y;
    a.x += b.x; a.y += b.y;
    b.x = dr * w.x - di * w.y;
    b.y = dr * w.y + di * w.x;
}
__device__ __forceinline__ float2 bfly_shfl(float2 v, int len, int lane, float2 w) {
    float ox = __shfl_xor_sync(0xffffffffu, v.x, len);
    float oy = __shfl_xor_sync(0xffffffffu, v.y, len);
    if ((lane & len) == 0) {
        return make_float2(v.x + ox, v.y + oy);
    } else {
        float dr = ox - v.x, di = oy - v.y;
        return make_float2(dr * w.x - di * w.y, dr * w.y + di * w.x);
    }
}
// tw[k] = exp(-i*pi*k/32)
__device__ __forceinline__ void fft64_reg(float2& a, float2& b, int lane,
                                          const float2* __restrict__ tw) {
    bfly_local(a, b, tw[lane]);
#pragma unroll
    for (int len = 16; len >= 1; len >>= 1) {
        float2 w = tw[(lane & (len - 1)) * (32 / len)];
        a = bfly_shfl(a, len, lane, w);
        b = bfly_shfl(b, len, lane, w);
    }
}

// ---- fused z + x FFT: one CTA per y-plane; zeroes d_grid; writes d_grid2 (same layout) ----
__global__ void __launch_bounds__(1024) k_fft_zx() {
    __shared__ float2 v[64 * 65];   // [x][z] at x*65+z
    __shared__ float2 tw[32];
    const int tid  = threadIdx.x;
    const int lane = tid & 31, w = tid >> 5;
    const int y0   = blockIdx.x << 6;           // y-plane base offset
    if (tid < 32) {
        float s, c; sincospif((float)tid / 32.f, &s, &c);
        tw[tid] = make_float2(c, -s);
    }
    const float2 zero2 = make_float2(0.f, 0.f);
    for (int k = tid; k < 4096; k += 1024) {
        int x = k >> 6, z = k & 63;
        int g = x * 4096 + y0 + z;              // contiguous 512B per x-chunk
        v[x * 65 + z] = d_grid[g];
        d_grid[g] = zero2;                      // restore spread invariant for next replay
    }
    __syncthreads();
    // z-FFTs: rows x = w, w+32
#pragma unroll
    for (int l = 0; l < 2; l++) {
        float2* p = v + (w + 32 * l) * 65;
        float2 a = p[lane], b = p[lane + 32];
        fft64_reg(a, b, lane, tw);
        p[lane] = a; p[lane + 32] = b;
    }
    __syncthreads();
    // x-FFTs: columns z = w, w+32
#pragma unroll
    for (int l = 0; l < 2; l++) {
        float2* p = v + (w + 32 * l);
        float2 a = p[lane * 65], b = p[(lane + 32) * 65];
        fft64_reg(a, b, lane, tw);
        p[lane * 65] = a; p[(lane + 32) * 65] = b;
    }
    __syncthreads();
    for (int k = tid; k < 4096; k += 1024) {
        int x = k >> 6, z = k & 63;
        d_grid2[x * 4096 + y0 + z] = v[x * 65 + z];
    }
}

__device__ __forceinline__ int brev6(int x) { return (int)(__brev((unsigned)x) >> 26); }

__device__ __forceinline__ float recip_contrib(float2 F, int mx, int my, int mz,
                                               const float* bm, float iLx, float iLy, float iLz) {
    float fx = (mx < 32) ? (float)mx : (float)(mx - 64);
    float fy = (my < 32) ? (float)my : (float)(my - 64);
    float fz = (mz < 32) ? (float)mz : (float)(mz - 64);
    float k0 = fx * iLx, k1 = fy * iLy, k2 = fz * iLz;
    float msq = k0*k0 + k1*k1 + k2*k2;
    if (msq <= 0.f) return 0.f;
    float infl = __expf(-(PI_F*PI_F) * msq / (ALPHA*ALPHA)) / msq;
    return infl * bm[mx] * bm[my] * bm[mz] * (F.x*F.x + F.y*F.y);
}

// ---- y FFT + reduction: stride-512B lines from d_grid2, no stores ----
__global__ void __launch_bounds__(256) k_fft_y_red(const float* __restrict__ box) {
    __shared__ float2 tw[32];
    __shared__ float  bm[64];
    __shared__ float  partial[8];
    const int tid  = threadIdx.x;
    const int lane = tid & 31, w = tid >> 5;   // 8 warps
    if (tid < 32) {
        float sn, cs; sincospif((float)tid / 32.f, &sn, &cs);
        tw[tid] = make_float2(cs, -sn);
    }
    if (tid < 64) {
        float th = 2.f * PI_F * (float)tid / (float)NGRID;
        float re = (1.f/6.f) + (2.f/3.f)*cosf(th) + (1.f/6.f)*cosf(2.f*th);
        float im = -((2.f/3.f)*sinf(th) + (1.f/6.f)*sinf(2.f*th));
        bm[tid] = 1.f / fmaxf(re*re + im*im, 1e-7f);
    }
    const float iLx = __fdividef(1.f, box[0]);
    const float iLy = __fdividef(1.f, box[4]);
    const float iLz = __fdividef(1.f, box[8]);
    __syncthreads();

    const int line = blockIdx.x * 8 + w;        // = x_storage*64 + z_storage
    const float2* p = d_grid2 + ((line >> 6) << 12) + (line & 63);
    float2 a = p[lane << 6], b = p[(lane + 32) << 6];   // stride 64 float2 = 512 B
    fft64_reg(a, b, lane, tw);

    const int mx = brev6(line >> 6);
    const int mz = brev6(line & 63);
    float val = recip_contrib(a, mx, brev6(lane),      mz, bm, iLx, iLy, iLz)
              + recip_contrib(b, mx, brev6(lane + 32), mz, bm, iLx, iLy, iLz);
#pragma unroll
    for (int off = 16; off > 0; off >>= 1)
        val += __shfl_down_sync(0xffffffffu, val, off);
    if (lane == 0) partial[w] = val;
    __syncthreads();
    if (tid < 8) {
        float x = partial[tid];
#pragma unroll
        for (int off = 4; off > 0; off >>= 1)
            x += __shfl_down_sync(0xffu, x, off);
        if (tid == 0) atomicAdd(&g_erec, (double)x);
    }
}

// ---------------- finalize: emit energy, reset accumulators for next replay ----------------
__global__ void k_final(float* __restrict__ out, const float* __restrict__ box) {
    double V = fabs((double)box[0] * (double)box[4] * (double)box[8]);
    double erec = (double)COULOMB / (2.0 * 3.14159265358979323846 * V) * g_erec;
    out[0] = (float)(g_edir + erec);
    g_edir = 0.0;
    g_erec = 0.0;
}

// ---------------- launch (fork direct onto side stream, join before final) -------------
extern "C" void kernel_launch(void* const* d_in, const int* in_sizes, int n_in,
                              void* d_out, int out_size) {
    (void)n_in; (void)out_size;
    const float* pos  = (const float*)d_in[0];
    const float* q    = (const float*)d_in[1];
    const float* box  = (const float*)d_in[2];
    const int*   excl = (const int*)d_in[3];
    const int N = in_sizes[1];

    static cudaStream_t s_side = nullptr;
    static cudaEvent_t  ev_fork = nullptr, ev_join = nullptr;
    if (!s_side) {
        cudaStreamCreateWithFlags(&s_side, cudaStreamNonBlocking);
        cudaEventCreateWithFlags(&ev_fork, cudaEventDisableTiming);
        cudaEventCreateWithFlags(&ev_join, cudaEventDisableTiming);
    }

    // fork: direct-space on side stream
    cudaEventRecord(ev_fork, 0);
    cudaStreamWaitEvent(s_side, ev_fork, 0);
    dim3 dgrid(N / DTILE, N / DTILE);
    k_direct<<<dgrid, DTILE, 0, s_side>>>(pos, q, excl, box, N);
    cudaEventRecord(ev_join, s_side);

    // main: reciprocal chain
    k_spread<<<(4 * N + 255) / 256, 256>>>(pos, q, box, N);
    k_fft_zx<<<64, 1024>>>();
    k_fft_y_red<<<512, 256>>>(box);

    cudaStreamWaitEvent(0, ev_join, 0);
    k_final<<<1, 1>>>((float*)d_out, box);
}

// round 16
// speedup vs baseline: 1.5651x; 1.5651x over previous
#include <cuda_runtime.h>
#include <math.h>

#define NGRID   64
#define NG3     (64*64*64)
#define ALPHA   0.34f
#define COULOMB 138.935456f
#define CUTOFF2 81.0f
#define PI_F    3.14159265358979323846f
#define DTILE   128

// ---------------- device scratch (zero-initialized at module load) ----------------
__device__ float2 d_grid[NG3];      // FFT grid; re-zeroed (coalesced) by k_final each run
__device__ double g_edir;           // reset by k_final each run
__device__ double g_erec;           // reset by k_final each run

// Abramowitz-Stegun 7.1.26: |err| <= 1.5e-7 absolute, x >= 0
__device__ __forceinline__ float fast_erfc(float x) {
    float t = __fdividef(1.0f, fmaf(0.3275911f, x, 1.0f));
    float p = fmaf(1.061405429f, t, -1.453152027f);
    p = fmaf(p, t, 1.421413741f);
    p = fmaf(p, t, -0.284496736f);
    p = fmaf(p, t, 0.254829592f);
    return p * t * __expf(-x * x);
}

// ---------------- direct space (triangular 128x128 tiles, orthorhombic) ----------------
__global__ void __launch_bounds__(DTILE) k_direct(const float* __restrict__ pos,
                                                  const float* __restrict__ q,
                                                  const int* __restrict__ excl,
                                                  const float* __restrict__ box, int N) {
    const int bi = blockIdx.x, bj = blockIdx.y;
    if (bj < bi) return;
    __shared__ float4 sp[DTILE];
    const int tx = threadIdx.x;
    const int i  = bi * DTILE + tx;
    const int jb = bj * DTILE;

    int jl = jb + tx;
    sp[tx] = make_float4(pos[3*jl + 0], pos[3*jl + 1], pos[3*jl + 2], q[jl]);
    __syncthreads();

    const float Lx = box[0], Ly = box[4], Lz = box[8];
    const float iLx = __fdividef(1.f, Lx), iLy = __fdividef(1.f, Ly), iLz = __fdividef(1.f, Lz);

    const float pxi = pos[3*i + 0], pyi = pos[3*i + 1], pzi = pos[3*i + 2];
    const float qi  = q[i];
    const int e0 = excl[2*i + 0];
    const int e1 = excl[2*i + 1];

    float pacc = 0.f;
#pragma unroll 4
    for (int jj = 0; jj < DTILE; jj++) {
        float4 pj = sp[jj];
        float dx = pxi - pj.x;
        float dy = pyi - pj.y;
        float dz = pzi - pj.z;
        dx -= Lx * rintf(dx * iLx);
        dy -= Ly * rintf(dy * iLy);
        dz -= Lz * rintf(dz * iLz);
        float r2 = dx*dx + dy*dy + dz*dz;
        int jg = jb + jj;
        if (r2 < CUTOFF2 && jg != i && jg != e0 && jg != e1) {
            float rinv = rsqrtf(r2);
            pacc += pj.w * fast_erfc(ALPHA * r2 * rinv) * rinv;
        }
    }
    pacc *= qi;

    float eacc = 0.f;
    if (bi == bj) {
        eacc += -COULOMB * ALPHA * 0.5641895835477563f * qi * qi;  // self
#pragma unroll
        for (int s = 0; s < 2; s++) {
            int e = (s == 0) ? e0 : e1;
            if (e >= 0) {
                float dx = pxi - pos[3*e + 0];
                float dy = pyi - pos[3*e + 1];
                float dz = pzi - pos[3*e + 2];
                dx -= Lx * rintf(dx * iLx);
                dy -= Ly * rintf(dy * iLy);
                dz -= Lz * rintf(dz * iLz);
                float r2 = dx*dx + dy*dy + dz*dz;
                if (r2 > 0.f) {
                    float rinv = rsqrtf(r2);
                    float r = r2 * rinv;
                    eacc += -0.5f * COULOMB * qi * q[e] * erff(ALPHA * r) * rinv;
                }
            }
        }
    }

    float wt = (bi == bj) ? 0.5f : 1.0f;
    float tot = COULOMB * wt * pacc + eacc;
#pragma unroll
    for (int off = 16; off > 0; off >>= 1)
        tot += __shfl_down_sync(0xffffffffu, tot, off);
    if ((tx & 31) == 0)
        atomicAdd(&g_edir, (double)tot);
}

// ------- B-spline spread (order 4), one thread per (atom, x-offset, y-offset) -------
__global__ void k_spread(const float* __restrict__ pos, const float* __restrict__ q,
                         const float* __restrict__ box, int N) {
    int idx = blockIdx.x * blockDim.x + threadIdx.x;
    int i = idx >> 4;
    int a = (idx >> 2) & 3;
    int b = idx & 3;
    if (i >= N) return;

    const float iLx = __fdividef(1.f, box[0]);
    const float iLy = __fdividef(1.f, box[4]);
    const float iLz = __fdividef(1.f, box[8]);

    float f0 = pos[3*i + 0] * iLx;
    float f1 = pos[3*i + 1] * iLy;
    float f2 = pos[3*i + 2] * iLz;
    f0 -= floorf(f0); f1 -= floorf(f1); f2 -= floorf(f2);

    float u[3] = { f0 * NGRID, f1 * NGRID, f2 * NGRID };
    int   base[3];
    float w[3][4];
#pragma unroll
    for (int d = 0; d < 3; d++) {
        float fu = floorf(u[d]);
        base[d] = (int)fu;
        float t = u[d] - fu;
        float w2_0 = 1.f - t, w2_1 = t;
        float n0 = 0.5f * (1.f - t) * w2_0;
        float n1 = 0.5f * ((t + 1.f) * w2_0 + (2.f - t) * w2_1);
        float n2 = 0.5f * t * w2_1;
        w[d][3] = (1.f/3.f) * t * n2;
        w[d][2] = (1.f/3.f) * ((t + 1.f) * n1 + (3.f - t) * n2);
        w[d][1] = (1.f/3.f) * ((t + 2.f) * n0 + (2.f - t) * n1);
        w[d][0] = (1.f/3.f) * (1.f - t) * n0;
    }
    int ix = (base[0] + a + 61) & 63;
    int iy = (base[1] + b + 61) & 63;
    float qab = q[i] * w[0][a] * w[1][b];
#pragma unroll
    for (int c = 0; c < 4; c++) {
        int iz = (base[2] + c + 61) & 63;
        int flat = ((ix << 6) | iy) << 6 | iz;
        atomicAdd(&d_grid[flat].x, qab * w[2][c]);
    }
}

// ---------------- register-resident 64-pt DIF FFT (warp collective, out bit-reversed) ----
__device__ __forceinline__ void bfly_local(float2& a, float2& b, float2 w) {
    float dr = a.x - b.x, di = a.y - b.y;
    a.x += b.x; a.y += b.y;
    b.x = dr * w.x - di * w.y;
    b.y = dr * w.y + di * w.x;
}
__device__ __forceinline__ float2 bfly_shfl(float2 v, int len, int lane, float2 w) {
    float ox = __shfl_xor_sync(0xffffffffu, v.x, len);
    float oy = __shfl_xor_sync(0xffffffffu, v.y, len);
    if ((lane & len) == 0) {
        return make_float2(v.x + ox, v.y + oy);
    } else {
        float dr = ox - v.x, di = oy - v.y;
        return make_float2(dr * w.x - di * w.y, dr * w.y + di * w.x);
    }
}
// tw[k] = exp(-i*pi*k/32)
__device__ __forceinline__ void fft64_reg(float2& a, float2& b, int lane,
                                          const float2* __restrict__ tw) {
    bfly_local(a, b, tw[lane]);
#pragma unroll
    for (int len = 16; len >= 1; len >>= 1) {
        float2 w = tw[(lane & (len - 1)) * (32 / len)];
        a = bfly_shfl(a, len, lane, w);
        b = bfly_shfl(b, len, lane, w);
    }
}

// ---------------- fused z + y FFT passes: one CTA per x-plane, 32 warps (in-place) -----
__global__ void __launch_bounds__(1024) k_fft_zy() {
    __shared__ float2 v[64 * 65];
    __shared__ float2 tw[32];
    const int tid  = threadIdx.x;
    const int lane = tid & 31, w = tid >> 5;
    if (tid < 32) {
        float s, c; sincospif((float)tid / 32.f, &s, &c);
        tw[tid] = make_float2(c, -s);
    }
    float2* gp = d_grid + (blockIdx.x << 12);
    for (int k = tid; k < 4096; k += 1024) {
        int y = k >> 6, z = k & 63;
        v[y * 65 + z] = gp[k];
    }
    __syncthreads();
#pragma unroll
    for (int l = 0; l < 2; l++) {
        float2* p = v + (w + 32 * l) * 65;
        float2 a = p[lane], b = p[lane + 32];
        fft64_reg(a, b, lane, tw);
        p[lane] = a; p[lane + 32] = b;
    }
    __syncthreads();
#pragma unroll
    for (int l = 0; l < 2; l++) {
        float2* p = v + (w + 32 * l);
        float2 a = p[lane * 65], b = p[(lane + 32) * 65];
        fft64_reg(a, b, lane, tw);
        p[lane * 65] = a; p[(lane + 32) * 65] = b;
    }
    __syncthreads();
    for (int k = tid; k < 4096; k += 1024) {
        int y = k >> 6, z = k & 63;
        gp[k] = v[y * 65 + z];
    }
}

__device__ __forceinline__ int brev6(int x) { return (int)(__brev((unsigned)x) >> 26); }

__device__ __forceinline__ float recip_contrib(float2 F, int mx, int my, int mz,
                                               const float* bm, float iLx, float iLy, float iLz) {
    float fx = (mx < 32) ? (float)mx : (float)(mx - 64);
    float fy = (my < 32) ? (float)my : (float)(my - 64);
    float fz = (mz < 32) ? (float)mz : (float)(mz - 64);
    float k0 = fx * iLx, k1 = fy * iLy, k2 = fz * iLz;
    float msq = k0*k0 + k1*k1 + k2*k2;
    if (msq <= 0.f) return 0.f;
    float infl = __expf(-(PI_F*PI_F) * msq / (ALPHA*ALPHA)) / msq;
    return infl * bm[mx] * bm[my] * bm[mz] * (F.x*F.x + F.y*F.y);
}

// ---- x FFT + reduction: 1 warp per line, strided loads, NO stores ----
__global__ void __launch_bounds__(256) k_fft_x_red(const float* __restrict__ box) {
    __shared__ float2 tw[32];
    __shared__ float  bm[64];
    __shared__ float  partial[8];
    const int tid  = threadIdx.x;
    const int lane = tid & 31, w = tid >> 5;   // 8 warps
    if (tid < 32) {
        float sn, cs; sincospif((float)tid / 32.f, &sn, &cs);
        tw[tid] = make_float2(cs, -sn);
    }
    if (tid < 64) {
        float th = 2.f * PI_F * (float)tid / (float)NGRID;
        float re = (1.f/6.f) + (2.f/3.f)*cosf(th) + (1.f/6.f)*cosf(2.f*th);
        float im = -((2.f/3.f)*sinf(th) + (1.f/6.f)*sinf(2.f*th));
        bm[tid] = 1.f / fmaxf(re*re + im*im, 1e-7f);
    }
    const float iLx = __fdividef(1.f, box[0]);
    const float iLy = __fdividef(1.f, box[4]);
    const float iLz = __fdividef(1.f, box[8]);
    __syncthreads();

    const int line = blockIdx.x * 8 + w;       // = y_storage*64 + z_storage
    float2 a = d_grid[lane * 4096 + line];
    float2 b = d_grid[(lane + 32) * 4096 + line];
    fft64_reg(a, b, lane, tw);

    const int my = brev6(line >> 6);
    const int mz = brev6(line & 63);
    float val = recip_contrib(a, brev6(lane),      my, mz, bm, iLx, iLy, iLz)
              + recip_contrib(b, brev6(lane + 32), my, mz, bm, iLx, iLy, iLz);
#pragma unroll
    for (int off = 16; off > 0; off >>= 1)
        val += __shfl_down_sync(0xffffffffu, val, off);
    if (lane == 0) partial[w] = val;
    __syncthreads();
    if (tid < 8) {
        float x = partial[tid];
#pragma unroll
        for (int off = 4; off > 0; off >>= 1)
            x += __shfl_down_sync(0xffu, x, off);
        if (tid == 0) atomicAdd(&g_erec, (double)x);
    }
}

// ------ finalize: emit energy + reset accumulators + coalesced grid re-zero ------
__global__ void __launch_bounds__(256) k_final(float* __restrict__ out,
                                               const float* __restrict__ box) {
    // each of 512 CTAs zeroes a contiguous 512-float2 slice (2 per thread)
    const int base = blockIdx.x * 512 + threadIdx.x;
    d_grid[base]       = make_float2(0.f, 0.f);
    d_grid[base + 256] = make_float2(0.f, 0.f);
    if (blockIdx.x == 0 && threadIdx.x == 0) {
        double V = fabs((double)box[0] * (double)box[4] * (double)box[8]);
        double erec = (double)COULOMB / (2.0 * 3.14159265358979323846 * V) * g_erec;
        out[0] = (float)(g_edir + erec);
        g_edir = 0.0;
        g_erec = 0.0;
    }
}

// ---------------- launch (fork direct onto side stream, join before final) -------------
extern "C" void kernel_launch(void* const* d_in, const int* in_sizes, int n_in,
                              void* d_out, int out_size) {
    (void)n_in; (void)out_size;
    const float* pos  = (const float*)d_in[0];
    const float* q    = (const float*)d_in[1];
    const float* box  = (const float*)d_in[2];
    const int*   excl = (const int*)d_in[3];
    const int N = in_sizes[1];

    static cudaStream_t s_side = nullptr;
    static cudaEvent_t  ev_fork = nullptr, ev_join = nullptr;
    if (!s_side) {
        cudaStreamCreateWithFlags(&s_side, cudaStreamNonBlocking);
        cudaEventCreateWithFlags(&ev_fork, cudaEventDisableTiming);
        cudaEventCreateWithFlags(&ev_join, cudaEventDisableTiming);
    }

    // fork: direct-space on side stream
    cudaEventRecord(ev_fork, 0);
    cudaStreamWaitEvent(s_side, ev_fork, 0);
    dim3 dgrid(N / DTILE, N / DTILE);
    k_direct<<<dgrid, DTILE, 0, s_side>>>(pos, q, excl, box, N);
    cudaEventRecord(ev_join, s_side);

    // main: reciprocal chain
    k_spread<<<(16 * N + 255) / 256, 256>>>(pos, q, box, N);
    k_fft_zy<<<64, 1024>>>();
    k_fft_x_red<<<512, 256>>>(box);

    cudaStreamWaitEvent(0, ev_join, 0);
    k_final<<<512, 256>>>((float*)d_out, box);
}

// round 17
// speedup vs baseline: 1.5668x; 1.0011x over previous
#include <cuda_runtime.h>
#include <math.h>

#define NGRID   64
#define NG3     (64*64*64)
#define ALPHA   0.34f
#define COULOMB 138.935456f
#define CUTOFF2 81.0f
#define PI_F    3.14159265358979323846f
#define DTILE   128

// ---------------- device scratch (zero-initialized at module load) ----------------
__device__ float2 d_grid[NG3];      // FFT grid; re-zeroed (coalesced) by k_final each run
__device__ double g_edir;           // reset by k_final each run
__device__ double g_erec;           // reset by k_final each run

// Abramowitz-Stegun 7.1.26: |err| <= 1.5e-7 absolute, x >= 0
__device__ __forceinline__ float fast_erfc(float x) {
    float t = __fdividef(1.0f, fmaf(0.3275911f, x, 1.0f));
    float p = fmaf(1.061405429f, t, -1.453152027f);
    p = fmaf(p, t, 1.421413741f);
    p = fmaf(p, t, -0.284496736f);
    p = fmaf(p, t, 0.254829592f);
    return p * t * __expf(-x * x);
}

// ---------------- direct space (triangular 128x128 tiles, orthorhombic) ----------------
__global__ void __launch_bounds__(DTILE) k_direct(const float* __restrict__ pos,
                                                  const float* __restrict__ q,
                                                  const int* __restrict__ excl,
                                                  const float* __restrict__ box, int N) {
    const int bi = blockIdx.x, bj = blockIdx.y;
    if (bj < bi) return;
    __shared__ float4 sp[DTILE];
    const int tx = threadIdx.x;
    const int i  = bi * DTILE + tx;
    const int jb = bj * DTILE;

    int jl = jb + tx;
    sp[tx] = make_float4(pos[3*jl + 0], pos[3*jl + 1], pos[3*jl + 2], q[jl]);
    __syncthreads();

    const float Lx = box[0], Ly = box[4], Lz = box[8];
    const float iLx = __fdividef(1.f, Lx), iLy = __fdividef(1.f, Ly), iLz = __fdividef(1.f, Lz);

    const float pxi = pos[3*i + 0], pyi = pos[3*i + 1], pzi = pos[3*i + 2];
    const float qi  = q[i];
    const int e0 = excl[2*i + 0];
    const int e1 = excl[2*i + 1];

    float pacc = 0.f;
#pragma unroll 4
    for (int jj = 0; jj < DTILE; jj++) {
        float4 pj = sp[jj];
        float dx = pxi - pj.x;
        float dy = pyi - pj.y;
        float dz = pzi - pj.z;
        dx -= Lx * rintf(dx * iLx);
        dy -= Ly * rintf(dy * iLy);
        dz -= Lz * rintf(dz * iLz);
        float r2 = dx*dx + dy*dy + dz*dz;
        int jg = jb + jj;
        if (r2 < CUTOFF2 && jg != i && jg != e0 && jg != e1) {
            float rinv = rsqrtf(r2);
            pacc += pj.w * fast_erfc(ALPHA * r2 * rinv) * rinv;
        }
    }
    pacc *= qi;

    float eacc = 0.f;
    if (bi == bj) {
        eacc += -COULOMB * ALPHA * 0.5641895835477563f * qi * qi;  // self
#pragma unroll
        for (int s = 0; s < 2; s++) {
            int e = (s == 0) ? e0 : e1;
            if (e >= 0) {
                float dx = pxi - pos[3*e + 0];
                float dy = pyi - pos[3*e + 1];
                float dz = pzi - pos[3*e + 2];
                dx -= Lx * rintf(dx * iLx);
                dy -= Ly * rintf(dy * iLy);
                dz -= Lz * rintf(dz * iLz);
                float r2 = dx*dx + dy*dy + dz*dz;
                if (r2 > 0.f) {
                    float rinv = rsqrtf(r2);
                    float r = r2 * rinv;
                    eacc += -0.5f * COULOMB * qi * q[e] * erff(ALPHA * r) * rinv;
                }
            }
        }
    }

    float wt = (bi == bj) ? 0.5f : 1.0f;
    float tot = COULOMB * wt * pacc + eacc;
#pragma unroll
    for (int off = 16; off > 0; off >>= 1)
        tot += __shfl_down_sync(0xffffffffu, tot, off);
    if ((tx & 31) == 0)
        atomicAdd(&g_edir, (double)tot);
}

// ------- B-spline spread (order 4), one thread per (atom, x-offset, y-offset) -------
__global__ void k_spread(const float* __restrict__ pos, const float* __restrict__ q,
                         const float* __restrict__ box, int N) {
    int idx = blockIdx.x * blockDim.x + threadIdx.x;
    int i = idx >> 4;
    int a = (idx >> 2) & 3;
    int b = idx & 3;
    if (i >= N) return;

    const float iLx = __fdividef(1.f, box[0]);
    const float iLy = __fdividef(1.f, box[4]);
    const float iLz = __fdividef(1.f, box[8]);

    float f0 = pos[3*i + 0] * iLx;
    float f1 = pos[3*i + 1] * iLy;
    float f2 = pos[3*i + 2] * iLz;
    f0 -= floorf(f0); f1 -= floorf(f1); f2 -= floorf(f2);

    float u[3] = { f0 * NGRID, f1 * NGRID, f2 * NGRID };
    int   base[3];
    float w[3][4];
#pragma unroll
    for (int d = 0; d < 3; d++) {
        float fu = floorf(u[d]);
        base[d] = (int)fu;
        float t = u[d] - fu;
        float w2_0 = 1.f - t, w2_1 = t;
        float n0 = 0.5f * (1.f - t) * w2_0;
        float n1 = 0.5f * ((t + 1.f) * w2_0 + (2.f - t) * w2_1);
        float n2 = 0.5f * t * w2_1;
        w[d][3] = (1.f/3.f) * t * n2;
        w[d][2] = (1.f/3.f) * ((t + 1.f) * n1 + (3.f - t) * n2);
        w[d][1] = (1.f/3.f) * ((t + 2.f) * n0 + (2.f - t) * n1);
        w[d][0] = (1.f/3.f) * (1.f - t) * n0;
    }
    int ix = (base[0] + a + 61) & 63;
    int iy = (base[1] + b + 61) & 63;
    float qab = q[i] * w[0][a] * w[1][b];
#pragma unroll
    for (int c = 0; c < 4; c++) {
        int iz = (base[2] + c + 61) & 63;
        int flat = ((ix << 6) | iy) << 6 | iz;
        atomicAdd(&d_grid[flat].x, qab * w[2][c]);
    }
}

// ---------------- register-resident 64-pt DIF FFT (warp collective, out bit-reversed) ----
__device__ __forceinline__ void bfly_local(float2& a, float2& b, float2 w) {
    float dr = a.x - b.x, di = a.y - b.y;
    a.x += b.x; a.y += b.y;
    b.x = dr * w.x - di * w.y;
    b.y = dr * w.y + di * w.x;
}
__device__ __forceinline__ float2 bfly_shfl(float2 v, int len, int lane, float2 w) {
    float ox = __shfl_xor_sync(0xffffffffu, v.x, len);
    float oy = __shfl_xor_sync(0xffffffffu, v.y, len);
    if ((lane & len) == 0) {
        return make_float2(v.x + ox, v.y + oy);
    } else {
        float dr = ox - v.x, di = oy - v.y;
        return make_float2(dr * w.x - di * w.y, dr * w.y + di * w.x);
    }
}
// tw[k] = exp(-i*pi*k/32)
__device__ __forceinline__ void fft64_reg(float2& a, float2& b, int lane,
                                          const float2* __restrict__ tw) {
    bfly_local(a, b, tw[lane]);
#pragma unroll
    for (int len = 16; len >= 1; len >>= 1) {
        float2 w = tw[(lane & (len - 1)) * (32 / len)];
        a = bfly_shfl(a, len, lane, w);
        b = bfly_shfl(b, len, lane, w);
    }
}

// ---------------- fused z + y FFT passes: one CTA per x-plane, 32 warps (in-place) -----
__global__ void __launch_bounds__(1024) k_fft_zy() {
    __shared__ float2 v[64 * 65];
    __shared__ float2 tw[32];
    const int tid  = threadIdx.x;
    const int lane = tid & 31, w = tid >> 5;
    if (tid < 32) {
        float s, c; sincospif((float)tid / 32.f, &s, &c);
        tw[tid] = make_float2(c, -s);
    }
    float4* gp4 = (float4*)(d_grid + (blockIdx.x << 12));
#pragma unroll
    for (int it = 0; it < 2; it++) {
        int k4 = it * 1024 + tid;          // 0..2047 float4s
        int y = k4 >> 5, z2 = k4 & 31;
        float4 t4 = gp4[k4];
        v[y * 65 + 2*z2]     = make_float2(t4.x, t4.y);
        v[y * 65 + 2*z2 + 1] = make_float2(t4.z, t4.w);
    }
    __syncthreads();
#pragma unroll
    for (int l = 0; l < 2; l++) {
        float2* p = v + (w + 32 * l) * 65;
        float2 a = p[lane], b = p[lane + 32];
        fft64_reg(a, b, lane, tw);
        p[lane] = a; p[lane + 32] = b;
    }
    __syncthreads();
#pragma unroll
    for (int l = 0; l < 2; l++) {
        float2* p = v + (w + 32 * l);
        float2 a = p[lane * 65], b = p[(lane + 32) * 65];
        fft64_reg(a, b, lane, tw);
        p[lane * 65] = a; p[(lane + 32) * 65] = b;
    }
    __syncthreads();
#pragma unroll
    for (int it = 0; it < 2; it++) {
        int k4 = it * 1024 + tid;
        int y = k4 >> 5, z2 = k4 & 31;
        float2 e0 = v[y * 65 + 2*z2];
        float2 e1 = v[y * 65 + 2*z2 + 1];
        gp4[k4] = make_float4(e0.x, e0.y, e1.x, e1.y);
    }
}

__device__ __forceinline__ int brev6(int x) { return (int)(__brev((unsigned)x) >> 26); }

__device__ __forceinline__ float recip_contrib(float2 F, int mx, int my, int mz,
                                               const float* bm, float iLx, float iLy, float iLz) {
    float fx = (mx < 32) ? (float)mx : (float)(mx - 64);
    float fy = (my < 32) ? (float)my : (float)(my - 64);
    float fz = (mz < 32) ? (float)mz : (float)(mz - 64);
    float k0 = fx * iLx, k1 = fy * iLy, k2 = fz * iLz;
    float msq = k0*k0 + k1*k1 + k2*k2;
    if (msq <= 0.f) return 0.f;
    float infl = __expf(-(PI_F*PI_F) * msq / (ALPHA*ALPHA)) / msq;
    return infl * bm[mx] * bm[my] * bm[mz] * (F.x*F.x + F.y*F.y);
}

// ---- x FFT + reduction: 2 lines per warp via float4 strided loads, NO stores ----
__global__ void __launch_bounds__(256) k_fft_x_red(const float* __restrict__ box) {
    __shared__ float2 tw[32];
    __shared__ float  bm[64];
    __shared__ float  partial[8];
    const int tid  = threadIdx.x;
    const int lane = tid & 31, w = tid >> 5;   // 8 warps
    if (tid < 32) {
        float sn, cs; sincospif((float)tid / 32.f, &sn, &cs);
        tw[tid] = make_float2(cs, -sn);
    }
    if (tid < 64) {
        float th = 2.f * PI_F * (float)tid / (float)NGRID;
        float re = (1.f/6.f) + (2.f/3.f)*cosf(th) + (1.f/6.f)*cosf(2.f*th);
        float im = -((2.f/3.f)*sinf(th) + (1.f/6.f)*sinf(2.f*th));
        bm[tid] = 1.f / fmaxf(re*re + im*im, 1e-7f);
    }
    const float iLx = __fdividef(1.f, box[0]);
    const float iLy = __fdividef(1.f, box[4]);
    const float iLz = __fdividef(1.f, box[8]);
    __syncthreads();

    const int lp = blockIdx.x * 8 + w;          // line pair 0..2047 -> lines 2lp, 2lp+1
    const float4* g4 = (const float4*)d_grid;   // float4 index = x*2048 + lp
    float4 A = g4[lane * 2048 + lp];
    float4 B = g4[(lane + 32) * 2048 + lp];
    float2 a0 = make_float2(A.x, A.y), a1 = make_float2(A.z, A.w);
    float2 b0 = make_float2(B.x, B.y), b1 = make_float2(B.z, B.w);
    fft64_reg(a0, b0, lane, tw);
    fft64_reg(a1, b1, lane, tw);

    const int line0 = 2 * lp, line1 = 2 * lp + 1;
    const int my0 = brev6(line0 >> 6), mz0 = brev6(line0 & 63);
    const int my1 = brev6(line1 >> 6), mz1 = brev6(line1 & 63);
    const int mxa = brev6(lane), mxb = brev6(lane + 32);
    float val = recip_contrib(a0, mxa, my0, mz0, bm, iLx, iLy, iLz)
              + recip_contrib(b0, mxb, my0, mz0, bm, iLx, iLy, iLz)
              + recip_contrib(a1, mxa, my1, mz1, bm, iLx, iLy, iLz)
              + recip_contrib(b1, mxb, my1, mz1, bm, iLx, iLy, iLz);
#pragma unroll
    for (int off = 16; off > 0; off >>= 1)
        val += __shfl_down_sync(0xffffffffu, val, off);
    if (lane == 0) partial[w] = val;
    __syncthreads();
    if (tid < 8) {
        float x = partial[tid];
#pragma unroll
        for (int off = 4; off > 0; off >>= 1)
            x += __shfl_down_sync(0xffu, x, off);
        if (tid == 0) atomicAdd(&g_erec, (double)x);
    }
}

// ------ finalize: emit energy + reset accumulators + coalesced grid re-zero ------
__global__ void __launch_bounds__(256) k_final(float* __restrict__ out,
                                               const float* __restrict__ box) {
    const int base = blockIdx.x * 512 + threadIdx.x;
    d_grid[base]       = make_float2(0.f, 0.f);
    d_grid[base + 256] = make_float2(0.f, 0.f);
    if (blockIdx.x == 0 && threadIdx.x == 0) {
        double V = fabs((double)box[0] * (double)box[4] * (double)box[8]);
        double erec = (double)COULOMB / (2.0 * 3.14159265358979323846 * V) * g_erec;
        out[0] = (float)(g_edir + erec);
        g_edir = 0.0;
        g_erec = 0.0;
    }
}

// ---------------- launch (fork direct onto side stream, join before final) -------------
extern "C" void kernel_launch(void* const* d_in, const int* in_sizes, int n_in,
                              void* d_out, int out_size) {
    (void)n_in; (void)out_size;
    const float* pos  = (const float*)d_in[0];
    const float* q    = (const float*)d_in[1];
    const float* box  = (const float*)d_in[2];
    const int*   excl = (const int*)d_in[3];
    const int N = in_sizes[1];

    static cudaStream_t s_side = nullptr;
    static cudaEvent_t  ev_fork = nullptr, ev_join = nullptr;
    if (!s_side) {
        cudaStreamCreateWithFlags(&s_side, cudaStreamNonBlocking);
        cudaEventCreateWithFlags(&ev_fork, cudaEventDisableTiming);
        cudaEventCreateWithFlags(&ev_join, cudaEventDisableTiming);
    }

    // fork: direct-space on side stream
    cudaEventRecord(ev_fork, 0);
    cudaStreamWaitEvent(s_side, ev_fork, 0);
    dim3 dgrid(N / DTILE, N / DTILE);
    k_direct<<<dgrid, DTILE, 0, s_side>>>(pos, q, excl, box, N);
    cudaEventRecord(ev_join, s_side);

    // main: reciprocal chain
    k_spread<<<(16 * N + 255) / 256, 256>>>(pos, q, box, N);
    k_fft_zy<<<64, 1024>>>();
    k_fft_x_red<<<256, 256>>>(box);

    cudaStreamWaitEvent(0, ev_join, 0);
    k_final<<<512, 256>>>((float*)d_out, box);
}